// round 5
// baseline (speedup 1.0000x reference)
#include <cuda_runtime.h>
#include <cstdint>

// Problem constants
#define B_     16
#define L_     1024
#define D_     256
#define PAST_  16
#define LQ_    (L_ - PAST_)   // 1008
#define NL_    3

#define O_ELEMS   ((size_t)B_ * LQ_ * 256)   // 4,128,768 floats

// ---- scratch (__device__ array: no cudaMalloc allowed) ----
__device__ float g_mid[(size_t)B_ * L_ * D_];

// =====================================================================
// helpers
// =====================================================================
__device__ __forceinline__ void load_row8(float* x, const float* base, int r, int c)
{
    if (r >= 0) {
        float4 v0 = *(const float4*)(base + (size_t)r * D_ + c);
        float4 v1 = *(const float4*)(base + (size_t)r * D_ + c + 4);
        x[0]=v0.x; x[1]=v0.y; x[2]=v0.z; x[3]=v0.w;
        x[4]=v1.x; x[5]=v1.y; x[6]=v1.z; x[7]=v1.w;
    } else {
        #pragma unroll
        for (int k = 0; k < 8; k++) x[k] = 0.f;
    }
}

__device__ __forceinline__ void dot2(const float* u, const float* v, float& p0, float& p1)
{
    float s0 = 0.f, s1 = 0.f;
    #pragma unroll
    for (int k = 0; k < 8; k++) {
        s0 = fmaf(u[k], u[k], s0);
        s1 = fmaf(u[k], v[k], s1);
    }
    #pragma unroll
    for (int o = 16; o; o >>= 1) {
        s0 += __shfl_xor_sync(0xffffffffu, s0, o);
        s1 += __shfl_xor_sync(0xffffffffu, s1, o);
    }
    p0 = s0; p1 = s1;
}

__device__ __forceinline__ void coef2(float p0, float p1, bool valid, float& a0, float& a1)
{
    if (valid) {
        float s0 = p0 * 0.0625f;
        float s1 = p1 * 0.0625f;
        float m  = fmaxf(s0, s1);
        float e0 = expf(s0 - m);
        float e1 = expf(s1 - m);
        float inv = 1.f / (e0 + e1);
        a0 = e0 * inv;
        a1 = e1 * inv;
    } else {
        a0 = 1.f; a1 = 0.f;
    }
}

// =====================================================================
// Kernel A: g_mid producer. One warp per (b,l). Writes g_mid only.
// =====================================================================
__global__ void __launch_bounds__(256)
mid_kernel(const float* __restrict__ inp)
{
    const int lane = threadIdx.x & 31;
    const int row  = blockIdx.x * 8 + (threadIdx.x >> 5);  // 0..16383
    const int b    = row >> 10;
    const int l    = row & (L_ - 1);
    const float* base = inp + (size_t)b * L_ * D_;
    const int c = lane * 8;

    float o1[4][8];
    #pragma unroll
    for (int t = 0; t < 4; t++) {
        int lh = l - 2 * t;
        float xh[8], xl[8];
        load_row8(xh, base, lh, c);
        load_row8(xl, base, lh - 1, c);
        float p0, p1; dot2(xh, xl, p0, p1);
        float b0, b1; coef2(p0, p1, lh >= 1, b0, b1);
        #pragma unroll
        for (int k = 0; k < 8; k++)
            o1[t][k] = fmaf(b0, xh[k], fmaf(b1, xl[k], xh[k]));
    }
    float o2[2][8];
    #pragma unroll
    for (int t = 0; t < 2; t++) {
        int lh = l - 4 * t;
        float p0, p1; dot2(o1[2 * t], o1[2 * t + 1], p0, p1);
        float b0, b1; coef2(p0, p1, lh >= 2, b0, b1);
        #pragma unroll
        for (int k = 0; k < 8; k++)
            o2[t][k] = fmaf(b0, o1[2 * t][k], fmaf(b1, o1[2 * t + 1][k], o1[2 * t][k]));
    }
    float p0, p1; dot2(o2[0], o2[1], p0, p1);
    float c0, c1; coef2(p0, p1, l >= 4, c0, c1);
    float out[8];
    #pragma unroll
    for (int k = 0; k < 8; k++)
        out[k] = fmaf(c0, o2[0][k], fmaf(c1, o2[1][k], o2[0][k]));
    float* g = g_mid + ((size_t)b * L_ + l) * D_ + c;
    *(float4*)(g)     = make_float4(out[0], out[1], out[2], out[3]);
    *(float4*)(g + 4) = make_float4(out[4], out[5], out[6], out[7]);
}

// =====================================================================
// Kernel B: attn_stack fill. One warp per attn row, recomputes its coefs.
// =====================================================================
__global__ void __launch_bounds__(256)
fill_kernel(const float* __restrict__ inp, float* __restrict__ attn_out)
{
    const int lane  = threadIdx.x & 31;
    const int row   = blockIdx.x * 8 + (threadIdx.x >> 5);   // 0..49151
    const int b     = row / (NL_ * L_);
    const int rem   = row - b * (NL_ * L_);
    const int layer = rem >> 10;
    const int l     = rem & (L_ - 1);
    const int d     = 1 << layer;
    const float* base = inp + (size_t)b * L_ * D_;
    const int c = lane * 8;

    float a0, a1;

    if (layer == 0) {
        float xh[8], xl[8];
        load_row8(xh, base, l, c);
        load_row8(xl, base, l - 1, c);
        float p0, p1; dot2(xh, xl, p0, p1);
        coef2(p0, p1, l >= 1, a0, a1);
    } else if (layer == 1) {
        float o1[2][8];
        #pragma unroll
        for (int t = 0; t < 2; t++) {
            int lh = l - 2 * t;
            float xh[8], xl[8];
            load_row8(xh, base, lh, c);
            load_row8(xl, base, lh - 1, c);
            float p0, p1; dot2(xh, xl, p0, p1);
            float b0, b1; coef2(p0, p1, lh >= 1, b0, b1);
            #pragma unroll
            for (int k = 0; k < 8; k++)
                o1[t][k] = fmaf(b0, xh[k], fmaf(b1, xl[k], xh[k]));
        }
        float p0, p1; dot2(o1[0], o1[1], p0, p1);
        coef2(p0, p1, l >= 2, a0, a1);
    } else {
        float o1[4][8];
        #pragma unroll
        for (int t = 0; t < 4; t++) {
            int lh = l - 2 * t;
            float xh[8], xl[8];
            load_row8(xh, base, lh, c);
            load_row8(xl, base, lh - 1, c);
            float p0, p1; dot2(xh, xl, p0, p1);
            float b0, b1; coef2(p0, p1, lh >= 1, b0, b1);
            #pragma unroll
            for (int k = 0; k < 8; k++)
                o1[t][k] = fmaf(b0, xh[k], fmaf(b1, xl[k], xh[k]));
        }
        float o2[2][8];
        #pragma unroll
        for (int t = 0; t < 2; t++) {
            int lh = l - 4 * t;
            float p0, p1; dot2(o1[2 * t], o1[2 * t + 1], p0, p1);
            float b0, b1; coef2(p0, p1, lh >= 2, b0, b1);
            #pragma unroll
            for (int k = 0; k < 8; k++)
                o2[t][k] = fmaf(b0, o1[2 * t][k], fmaf(b1, o1[2 * t + 1][k], o1[2 * t][k]));
        }
        float p0, p1; dot2(o2[0], o2[1], p0, p1);
        coef2(p0, p1, l >= 4, a0, a1);
    }

    const int c0 = l;
    const int c1 = l - d;
    float4* dst = (float4*)(attn_out + (size_t)row * L_);
    #pragma unroll
    for (int s = 0; s < 8; s++) {
        int q = lane + (s << 5);
        float4 v = make_float4(0.f, 0.f, 0.f, 0.f);
        if ((c0 >> 2) == q)              ((float*)&v)[c0 & 3] = a0;
        if (c1 >= 0 && (c1 >> 2) == q)   ((float*)&v)[c1 & 3] = a1;
        __stcs(dst + q, v);
    }
}

// =====================================================================
// Kernel C: o = g_mid[:,16:] @ W^T + bias + residual  (tf32 mma, pipelined)
// =====================================================================
#define GBM 128
#define GBN 128
#define GBK 32
#define SST 36

__device__ __forceinline__ unsigned f2tf32(float x) {
    unsigned u;
    asm("cvt.rna.tf32.f32 %0, %1;" : "=r"(u) : "f"(x));
    return u;
}

__device__ __forceinline__ void mma_tf32(float* c, const unsigned* a, const unsigned* b) {
    asm volatile(
        "mma.sync.aligned.m16n8k8.row.col.f32.tf32.tf32.f32 "
        "{%0,%1,%2,%3}, {%4,%5,%6,%7}, {%8,%9}, {%0,%1,%2,%3};"
        : "+f"(c[0]), "+f"(c[1]), "+f"(c[2]), "+f"(c[3])
        : "r"(a[0]), "r"(a[1]), "r"(a[2]), "r"(a[3]), "r"(b[0]), "r"(b[1]));
}

__global__ void __launch_bounds__(256)
gemm_tf32_kernel(const float* __restrict__ W, const float* __restrict__ bias,
                 const float* __restrict__ inp, float* __restrict__ o_out)
{
    __shared__ unsigned As[GBM * SST];
    __shared__ unsigned Bs[GBN * SST];

    const int tid  = threadIdx.x;
    const int m0   = blockIdx.x * GBM;
    const int n0   = blockIdx.y * GBN;
    const int wid  = tid >> 5;
    const int lane = tid & 31;
    const int warp_m = wid & 3;
    const int warp_n = wid >> 2;
    const int gid = lane >> 2;
    const int tig = lane & 3;

    float acc[2][8][4];
    #pragma unroll
    for (int i = 0; i < 2; i++)
        #pragma unroll
        for (int j = 0; j < 8; j++)
            #pragma unroll
            for (int k = 0; k < 4; k++) acc[i][j][k] = 0.f;

    // register prefetch buffers
    float4 aR[4], bR[4];
    int aRow[4];
    #pragma unroll
    for (int it = 0; it < 4; it++) {
        int idx = tid + it * 256;
        int r   = idx >> 3;
        int m   = m0 + r;
        int bb  = m / LQ_;
        aRow[it] = (int)((size_t)bb * L_ + (m - bb * LQ_ + PAST_));
    }

    // preload chunk 0
    #pragma unroll
    for (int it = 0; it < 4; it++) {
        int idx = tid + it * 256;
        int q   = idx & 7;
        aR[it] = *(const float4*)(g_mid + (size_t)aRow[it] * D_ + q * 4);
        int n  = idx >> 3;
        bR[it] = *(const float4*)(W + (size_t)(n0 + n) * 256 + q * 4);
    }

    for (int kc = 0; kc < 256; kc += GBK) {
        __syncthreads();
        #pragma unroll
        for (int it = 0; it < 4; it++) {
            int idx = tid + it * 256;
            int r   = idx >> 3;
            int q   = idx & 7;
            *(uint4*)(As + r * SST + q * 4) =
                make_uint4(f2tf32(aR[it].x), f2tf32(aR[it].y), f2tf32(aR[it].z), f2tf32(aR[it].w));
            *(uint4*)(Bs + r * SST + q * 4) =
                make_uint4(f2tf32(bR[it].x), f2tf32(bR[it].y), f2tf32(bR[it].z), f2tf32(bR[it].w));
        }
        __syncthreads();

        if (kc + GBK < 256) {
            #pragma unroll
            for (int it = 0; it < 4; it++) {
                int idx = tid + it * 256;
                int q   = idx & 7;
                aR[it] = *(const float4*)(g_mid + (size_t)aRow[it] * D_ + kc + GBK + q * 4);
                int n  = idx >> 3;
                bR[it] = *(const float4*)(W + (size_t)(n0 + n) * 256 + kc + GBK + q * 4);
            }
        }

        #pragma unroll
        for (int kk = 0; kk < GBK; kk += 8) {
            unsigned a[2][4], bq[8][2];
            #pragma unroll
            for (int mt = 0; mt < 2; mt++) {
                int r = warp_m * 32 + mt * 16 + gid;
                a[mt][0] = As[r * SST + kk + tig];
                a[mt][1] = As[(r + 8) * SST + kk + tig];
                a[mt][2] = As[r * SST + kk + tig + 4];
                a[mt][3] = As[(r + 8) * SST + kk + tig + 4];
            }
            #pragma unroll
            for (int nt = 0; nt < 8; nt++) {
                int cix = warp_n * 64 + nt * 8 + gid;
                bq[nt][0] = Bs[cix * SST + kk + tig];
                bq[nt][1] = Bs[cix * SST + kk + tig + 4];
            }
            #pragma unroll
            for (int mt = 0; mt < 2; mt++)
                #pragma unroll
                for (int nt = 0; nt < 8; nt++)
                    mma_tf32(acc[mt][nt], a[mt], bq[nt]);
        }
    }

    #pragma unroll
    for (int mt = 0; mt < 2; mt++) {
        #pragma unroll
        for (int half = 0; half < 2; half++) {
            int m  = m0 + warp_m * 32 + mt * 16 + gid + half * 8;
            int bb = m / LQ_;
            int lq = m - bb * LQ_;
            const float* res = inp + ((size_t)bb * L_ + lq + PAST_) * D_;
            float* orow = o_out + (size_t)m * 256;
            #pragma unroll
            for (int nt = 0; nt < 8; nt++) {
                int col = n0 + warp_n * 64 + nt * 8 + 2 * tig;
                float v0 = acc[mt][nt][half * 2 + 0] + bias[col]     + res[col & 63];
                float v1 = acc[mt][nt][half * 2 + 1] + bias[col + 1] + res[(col + 1) & 63];
                __stcs((float2*)(orow + col), make_float2(v0, v1));
            }
        }
    }
}

// =====================================================================
// launch: fork fill onto a low-priority stream; mid -> gemm on default.
// Streams/events created at static init (no device memory allocation).
// =====================================================================
static cudaStream_t g_s2 = 0;
static cudaEvent_t  g_fork = 0, g_join = 0;
static struct StreamInit {
    StreamInit() {
        int lo = 0, hi = 0;
        cudaDeviceGetStreamPriorityRange(&lo, &hi);   // lo = least priority
        cudaStreamCreateWithPriority(&g_s2, cudaStreamNonBlocking, lo);
        cudaEventCreateWithFlags(&g_fork, cudaEventDisableTiming);
        cudaEventCreateWithFlags(&g_join, cudaEventDisableTiming);
    }
} g_stream_init;

extern "C" void kernel_launch(void* const* d_in, const int* in_sizes, int n_in,
                              void* d_out, int out_size)
{
    const float* inp  = (const float*)d_in[0];
    const float* W    = (const float*)d_in[1];
    const float* bias = (const float*)d_in[2];
    // d_in[3] = masks : compile-time structure, unused

    float* out  = (float*)d_out;           // o : (16, 1008, 4, 64)
    float* attn = out + O_ELEMS;           // attn_stack : (16, 3, 1024, 1024)

    // fork: fill runs concurrently with (mid -> gemm)
    cudaEventRecord(g_fork, 0);
    cudaStreamWaitEvent(g_s2, g_fork, 0);

    fill_kernel<<<(B_ * NL_ * L_) / 8, 256, 0, g_s2>>>(inp, attn);

    mid_kernel<<<(B_ * L_) / 8, 256>>>(inp);
    gemm_tf32_kernel<<<dim3((B_ * LQ_) / GBM, 256 / GBN), 256>>>(W, bias, inp, out);

    // join
    cudaEventRecord(g_join, g_s2);
    cudaStreamWaitEvent(0, g_join, 0);
}

// round 6
// speedup vs baseline: 1.3398x; 1.3398x over previous
#include <cuda_runtime.h>
#include <cstdint>

// Problem constants
#define B_     16
#define L_     1024
#define D_     256
#define PAST_  16
#define LQ_    (L_ - PAST_)   // 1008
#define NL_    3

#define O_ELEMS   ((size_t)B_ * LQ_ * 256)   // 4,128,768 floats

// ---- scratch (__device__ arrays: no cudaMalloc allowed) ----
__device__ unsigned g_mid32[(size_t)B_ * L_ * D_];   // post-attn activations, tf32 bits
__device__ unsigned g_wtf[256 * 256];                // W pre-converted to tf32 bits

__device__ __forceinline__ unsigned f2tf32(float x) {
    unsigned u;
    asm("cvt.rna.tf32.f32 %0, %1;" : "=r"(u) : "f"(x));
    return u;
}

// =====================================================================
// helpers
// =====================================================================
__device__ __forceinline__ void load_row8(float* x, const float* base, int r, int c)
{
    if (r >= 0) {
        float4 v0 = *(const float4*)(base + (size_t)r * D_ + c);
        float4 v1 = *(const float4*)(base + (size_t)r * D_ + c + 4);
        x[0]=v0.x; x[1]=v0.y; x[2]=v0.z; x[3]=v0.w;
        x[4]=v1.x; x[5]=v1.y; x[6]=v1.z; x[7]=v1.w;
    } else {
        #pragma unroll
        for (int k = 0; k < 8; k++) x[k] = 0.f;
    }
}

__device__ __forceinline__ void dot2(const float* u, const float* v, float& p0, float& p1)
{
    float s0 = 0.f, s1 = 0.f;
    #pragma unroll
    for (int k = 0; k < 8; k++) {
        s0 = fmaf(u[k], u[k], s0);
        s1 = fmaf(u[k], v[k], s1);
    }
    #pragma unroll
    for (int o = 16; o; o >>= 1) {
        s0 += __shfl_xor_sync(0xffffffffu, s0, o);
        s1 += __shfl_xor_sync(0xffffffffu, s1, o);
    }
    p0 = s0; p1 = s1;
}

__device__ __forceinline__ void coef2(float p0, float p1, bool valid, float& a0, float& a1)
{
    if (valid) {
        float s0 = p0 * 0.0625f;   // 1/sqrt(256)
        float s1 = p1 * 0.0625f;
        float m  = fmaxf(s0, s1);
        float e0 = expf(s0 - m);
        float e1 = expf(s1 - m);
        float inv = 1.f / (e0 + e1);
        a0 = e0 * inv;
        a1 = e1 * inv;
    } else {
        a0 = 1.f; a1 = 0.f;
    }
}

// =====================================================================
// Kernel 1: one warp per (b,l). Computes the full 3-layer chain once,
// writes 3 attn rows + the g_mid row (tf32 bits). Block 2048 converts W.
// =====================================================================
__global__ void __launch_bounds__(256)
fill_kernel(const float* __restrict__ inp, const float* __restrict__ W,
            float* __restrict__ attn_out)
{
    if (blockIdx.x == (B_ * L_) / 8) {
        // W -> tf32 conversion block
        const int tid = threadIdx.x;
        #pragma unroll 4
        for (int i = tid * 4; i < 256 * 256; i += 256 * 4) {
            float4 v = *(const float4*)(W + i);
            *(uint4*)(g_wtf + i) =
                make_uint4(f2tf32(v.x), f2tf32(v.y), f2tf32(v.z), f2tf32(v.w));
        }
        return;
    }

    const int lane = threadIdx.x & 31;
    const int row  = blockIdx.x * 8 + (threadIdx.x >> 5);  // 0..16383
    const int b    = row >> 10;
    const int l    = row & (L_ - 1);
    const float* base = inp + (size_t)b * L_ * D_;
    const int c = lane * 8;

    float A0[NL_], A1[NL_];   // per-layer coefficients for row l

    // layer 0 chains at l, l-2, l-4, l-6
    float o1[4][8];
    #pragma unroll
    for (int t = 0; t < 4; t++) {
        int lh = l - 2 * t;
        float xh[8], xl[8];
        load_row8(xh, base, lh, c);
        load_row8(xl, base, lh - 1, c);
        float p0, p1; dot2(xh, xl, p0, p1);
        float b0, b1; coef2(p0, p1, lh >= 1, b0, b1);
        #pragma unroll
        for (int k = 0; k < 8; k++)
            o1[t][k] = fmaf(b0, xh[k], fmaf(b1, xl[k], xh[k]));
        if (t == 0) { A0[0] = b0; A1[0] = b1; }
    }
    // layer 1 at l, l-4
    float o2[2][8];
    #pragma unroll
    for (int t = 0; t < 2; t++) {
        int lh = l - 4 * t;
        float p0, p1; dot2(o1[2 * t], o1[2 * t + 1], p0, p1);
        float b0, b1; coef2(p0, p1, lh >= 2, b0, b1);
        #pragma unroll
        for (int k = 0; k < 8; k++)
            o2[t][k] = fmaf(b0, o1[2 * t][k], fmaf(b1, o1[2 * t + 1][k], o1[2 * t][k]));
        if (t == 0) { A0[1] = b0; A1[1] = b1; }
    }
    // layer 2 at l
    {
        float p0, p1; dot2(o2[0], o2[1], p0, p1);
        float c0, c1; coef2(p0, p1, l >= 4, c0, c1);
        A0[2] = c0; A1[2] = c1;
        float out[8];
        #pragma unroll
        for (int k = 0; k < 8; k++)
            out[k] = fmaf(c0, o2[0][k], fmaf(c1, o2[1][k], o2[0][k]));
        unsigned* g = g_mid32 + ((size_t)b * L_ + l) * D_ + c;
        *(uint4*)(g)     = make_uint4(f2tf32(out[0]), f2tf32(out[1]), f2tf32(out[2]), f2tf32(out[3]));
        *(uint4*)(g + 4) = make_uint4(f2tf32(out[4]), f2tf32(out[5]), f2tf32(out[6]), f2tf32(out[7]));
    }

    // ---- stream 3 attn rows (zeros + 2 injected values each) ----
    #pragma unroll
    for (int layer = 0; layer < NL_; layer++) {
        const int d  = 1 << layer;
        const int c0 = l;
        const int c1 = l - d;
        const float a0 = A0[layer];
        const float a1 = A1[layer];
        float4* dst = (float4*)(attn_out + ((size_t)(b * NL_ + layer) * L_ + l) * L_);
        #pragma unroll
        for (int s = 0; s < 8; s++) {
            int q = lane + (s << 5);
            float4 v = make_float4(0.f, 0.f, 0.f, 0.f);
            if ((c0 >> 2) == q)              ((float*)&v)[c0 & 3] = a0;
            if (c1 >= 0 && (c1 >> 2) == q)   ((float*)&v)[c1 & 3] = a1;
            __stcs(dst + q, v);
        }
    }
}

// =====================================================================
// Kernel 2: o = g_mid[:,16:] @ W^T + bias + residual
// tf32 mma.sync, cp.async double-buffered smem pipeline
// =====================================================================
#define GBM 128
#define GBN 128
#define GBK 32
#define SST 36
#define STAGE_W (GBM * SST)      // words per matrix per stage (A and B equal)

__device__ __forceinline__ void cp_async16(unsigned* smem_ptr, const unsigned* gptr) {
    unsigned saddr = (unsigned)__cvta_generic_to_shared(smem_ptr);
    asm volatile("cp.async.cg.shared.global [%0], [%1], 16;" :: "r"(saddr), "l"(gptr));
}
__device__ __forceinline__ void cp_commit() {
    asm volatile("cp.async.commit_group;");
}
template<int N> __device__ __forceinline__ void cp_wait() {
    asm volatile("cp.async.wait_group %0;" :: "n"(N));
}

__device__ __forceinline__ void mma_tf32(float* c, const unsigned* a, const unsigned* b) {
    asm volatile(
        "mma.sync.aligned.m16n8k8.row.col.f32.tf32.tf32.f32 "
        "{%0,%1,%2,%3}, {%4,%5,%6,%7}, {%8,%9}, {%0,%1,%2,%3};"
        : "+f"(c[0]), "+f"(c[1]), "+f"(c[2]), "+f"(c[3])
        : "r"(a[0]), "r"(a[1]), "r"(a[2]), "r"(a[3]), "r"(b[0]), "r"(b[1]));
}

__global__ void __launch_bounds__(256, 2)
gemm_tf32_kernel(const float* __restrict__ bias,
                 const float* __restrict__ inp, float* __restrict__ o_out)
{
    extern __shared__ unsigned sh[];
    unsigned* AsBase = sh;                  // [2][STAGE_W]
    unsigned* BsBase = sh + 2 * STAGE_W;    // [2][STAGE_W]

    const int tid  = threadIdx.x;
    const int m0   = blockIdx.x * GBM;
    const int n0   = blockIdx.y * GBN;
    const int wid  = tid >> 5;
    const int lane = tid & 31;
    const int warp_m = wid & 3;    // 4 warps in M (32 rows each)
    const int warp_n = wid >> 2;   // 2 warps in N (64 cols each)
    const int gid = lane >> 2;
    const int tig = lane & 3;

    // per-thread load descriptors (4 float4 loads per matrix per stage)
    const unsigned* aPtr[4];
    const unsigned* bPtr[4];
    int sOff[4];
    #pragma unroll
    for (int it = 0; it < 4; it++) {
        int idx = tid + it * 256;
        int r   = idx >> 3;          // row (A) / col (B)
        int q   = idx & 7;
        int m   = m0 + r;
        int bb  = m / LQ_;
        int gl  = (int)((size_t)bb * L_ + (m - bb * LQ_ + PAST_));
        aPtr[it] = g_mid32 + (size_t)gl * D_ + q * 4;
        bPtr[it] = g_wtf + (size_t)(n0 + r) * 256 + q * 4;
        sOff[it] = r * SST + q * 4;
    }

    float acc[2][8][4];
    #pragma unroll
    for (int i = 0; i < 2; i++)
        #pragma unroll
        for (int j = 0; j < 8; j++)
            #pragma unroll
            for (int k = 0; k < 4; k++) acc[i][j][k] = 0.f;

    // prologue: stage 0 loads for kc=0
    #pragma unroll
    for (int it = 0; it < 4; it++) {
        cp_async16(AsBase + sOff[it], aPtr[it]);
        cp_async16(BsBase + sOff[it], bPtr[it]);
    }
    cp_commit();

    #pragma unroll
    for (int i = 0; i < 8; i++) {
        // issue next stage (smem stage (i+1)&1 was last read in iter i-1, sync'd)
        if (i < 7) {
            unsigned* As = AsBase + ((i + 1) & 1) * STAGE_W;
            unsigned* Bs = BsBase + ((i + 1) & 1) * STAGE_W;
            int kc = (i + 1) * GBK;
            #pragma unroll
            for (int it = 0; it < 4; it++) {
                cp_async16(As + sOff[it], aPtr[it] + kc);
                cp_async16(Bs + sOff[it], bPtr[it] + kc);
            }
            cp_commit();
            cp_wait<1>();
        } else {
            cp_wait<0>();
        }
        __syncthreads();

        const unsigned* As = AsBase + (i & 1) * STAGE_W;
        const unsigned* Bs = BsBase + (i & 1) * STAGE_W;
        #pragma unroll
        for (int kk = 0; kk < GBK; kk += 8) {
            unsigned a[2][4], bq[8][2];
            #pragma unroll
            for (int mt = 0; mt < 2; mt++) {
                int r = warp_m * 32 + mt * 16 + gid;
                a[mt][0] = As[r * SST + kk + tig];
                a[mt][1] = As[(r + 8) * SST + kk + tig];
                a[mt][2] = As[r * SST + kk + tig + 4];
                a[mt][3] = As[(r + 8) * SST + kk + tig + 4];
            }
            #pragma unroll
            for (int nt = 0; nt < 8; nt++) {
                int cix = warp_n * 64 + nt * 8 + gid;
                bq[nt][0] = Bs[cix * SST + kk + tig];
                bq[nt][1] = Bs[cix * SST + kk + tig + 4];
            }
            #pragma unroll
            for (int mt = 0; mt < 2; mt++)
                #pragma unroll
                for (int nt = 0; nt < 8; nt++)
                    mma_tf32(acc[mt][nt], a[mt], bq[nt]);
        }
        __syncthreads();
    }

    // Epilogue: + bias + residual inp[b, lq+16, col&63]
    #pragma unroll
    for (int mt = 0; mt < 2; mt++) {
        #pragma unroll
        for (int half = 0; half < 2; half++) {
            int m  = m0 + warp_m * 32 + mt * 16 + gid + half * 8;
            int bb = m / LQ_;
            int lq = m - bb * LQ_;
            const float* res = inp + ((size_t)bb * L_ + lq + PAST_) * D_;
            float* orow = o_out + (size_t)m * 256;
            #pragma unroll
            for (int nt = 0; nt < 8; nt++) {
                int col = n0 + warp_n * 64 + nt * 8 + 2 * tig;
                float v0 = acc[mt][nt][half * 2 + 0] + bias[col]     + res[col & 63];
                float v1 = acc[mt][nt][half * 2 + 1] + bias[col + 1] + res[(col + 1) & 63];
                __stcs((float2*)(orow + col), make_float2(v0, v1));
            }
        }
    }
}

extern "C" void kernel_launch(void* const* d_in, const int* in_sizes, int n_in,
                              void* d_out, int out_size)
{
    const float* inp  = (const float*)d_in[0];
    const float* W    = (const float*)d_in[1];
    const float* bias = (const float*)d_in[2];
    // d_in[3] = masks : compile-time structure, unused

    float* out  = (float*)d_out;           // o : (16, 1008, 4, 64)
    float* attn = out + O_ELEMS;           // attn_stack : (16, 3, 1024, 1024)

    const int smem2 = 4 * STAGE_W * (int)sizeof(unsigned);   // 73,728 B
    cudaFuncSetAttribute(gemm_tf32_kernel,
                         cudaFuncAttributeMaxDynamicSharedMemorySize, smem2);

    fill_kernel<<<(B_ * L_) / 8 + 1, 256>>>(inp, W, attn);
    gemm_tf32_kernel<<<dim3((B_ * LQ_) / GBM, 256 / GBN), 256, smem2>>>(bias, inp, out);
}